// round 1
// baseline (speedup 1.0000x reference)
#include <cuda_runtime.h>

#define BATCHN 8192
#define SEQ 100
#define EMBED 50
#define HID 20
#define NLABEL 15
#define G3 60
#define WARPS 4
#define RPW 4

typedef unsigned long long ull;

__device__ __forceinline__ ull pack2(float x) {
    ull d; asm("mov.b64 %0, {%1, %1};" : "=l"(d) : "f"(x)); return d;
}
__device__ __forceinline__ ull packab(float a, float b) {
    ull d; asm("mov.b64 %0, {%1, %2};" : "=l"(d) : "f"(a), "f"(b)); return d;
}
__device__ __forceinline__ void unpk(ull v, float &a, float &b) {
    asm("mov.b64 {%0, %1}, %2;" : "=f"(a), "=f"(b) : "l"(v));
}
// Packed dual-FMA: lo(d)=lo(a)*lo(b)+lo(c), hi likewise. sm_100+ only, PTX-only path.
__device__ __forceinline__ ull ffma2(ull a, ull b, ull c) {
    ull d; asm("fma.rn.f32x2 %0, %1, %2, %3;" : "=l"(d) : "l"(a), "l"(b), "l"(c)); return d;
}

__device__ __forceinline__ float sigm(float x) {
    return __fdividef(1.f, 1.f + __expf(-x));
}
__device__ __forceinline__ float tanh_(float x) {
    return 2.f * __fdividef(1.f, 1.f + __expf(-2.f * x)) - 1.f;
}

__global__ void __launch_bounds__(128) wordrnn_kernel(
    const int* __restrict__ xg, const float* __restrict__ emb,
    const float* __restrict__ W1, const float* __restrict__ U1, const float* __restrict__ b1,
    const float* __restrict__ W2, const float* __restrict__ U2, const float* __restrict__ b2,
    const float* __restrict__ Wd, const float* __restrict__ bd,
    float* __restrict__ out)
{
    // Weights padded to 64 gate columns, stored as packed pairs (col j, col j+32).
    __shared__ ull sW1p[EMBED][32];
    __shared__ ull sU1p[HID][32];
    __shared__ ull sW2p[HID][32];
    __shared__ ull sU2p[HID][32];
    __shared__ ull sb1i[32], sb1r[32], sb2i[32], sb2r[32];
    __shared__ float sWd[HID][16];
    __shared__ float sbd[16];
    // Per-warp scratch (warp-private; only __syncwarp in the hot loop).
    __shared__ ull   shx[WARPS][RPW][EMBED]; // embedding, duplicated-packed
    __shared__ ull   sh1[WARPS][RPW][HID];   // h1 state, duplicated-packed
    __shared__ ull   sh2[WARPS][RPW][HID];   // h2 state, duplicated-packed
    __shared__ float ss [WARPS][RPW][64];    // z,r sums; h-gate mx part
    __shared__ float smh[WARPS][RPW][24];    // h-gate mh part (cols 40..63)
    __shared__ int   sidx[WARPS][RPW];

    const int tid = threadIdx.x;
    const int w = tid >> 5;
    const int j = tid & 31;

    // ---- stage weights into shared (packed pair layout) ----
    for (int i = tid; i < EMBED * 32; i += blockDim.x) {
        int k = i >> 5, c = i & 31;
        float lo = W1[k * G3 + c];
        float hi = (c + 32 < G3) ? W1[k * G3 + c + 32] : 0.f;
        sW1p[k][c] = packab(lo, hi);
    }
    for (int i = tid; i < HID * 32; i += blockDim.x) {
        int k = i >> 5, c = i & 31;
        float lo, hi;
        lo = U1[k * G3 + c]; hi = (c + 32 < G3) ? U1[k * G3 + c + 32] : 0.f;
        sU1p[k][c] = packab(lo, hi);
        lo = W2[k * G3 + c]; hi = (c + 32 < G3) ? W2[k * G3 + c + 32] : 0.f;
        sW2p[k][c] = packab(lo, hi);
        lo = U2[k * G3 + c]; hi = (c + 32 < G3) ? U2[k * G3 + c + 32] : 0.f;
        sU2p[k][c] = packab(lo, hi);
    }
    if (tid < 32) {
        int c = tid;
        float lo, hi;
        lo = b1[c];      hi = (c + 32 < G3) ? b1[c + 32]      : 0.f; sb1i[c] = packab(lo, hi);
        lo = b1[60 + c]; hi = (c + 32 < G3) ? b1[60 + c + 32] : 0.f; sb1r[c] = packab(lo, hi);
        lo = b2[c];      hi = (c + 32 < G3) ? b2[c + 32]      : 0.f; sb2i[c] = packab(lo, hi);
        lo = b2[60 + c]; hi = (c + 32 < G3) ? b2[60 + c + 32] : 0.f; sb2r[c] = packab(lo, hi);
    }
    for (int i = tid; i < HID * NLABEL; i += blockDim.x)
        sWd[i / NLABEL][i % NLABEL] = Wd[i];
    if (tid < NLABEL) sbd[tid] = bd[tid];
    for (int i = tid; i < WARPS * RPW * HID; i += blockDim.x) {
        ((ull*)sh1)[i] = 0ull;
        ((ull*)sh2)[i] = 0ull;
    }
    __syncthreads();

    const int b0 = (blockIdx.x * WARPS + w) * RPW;
    const ull bz1 = sb1i[j], br1 = sb1r[j], bz2 = sb2i[j], br2 = sb2r[j];

    for (int t = 0; t < SEQ; t++) {
        // ---- phase A: gather indices + embedding rows (duplicated-packed) ----
        if (j < RPW) sidx[w][j] = xg[(b0 + j) * SEQ + t];
        __syncwarp();
        for (int i = j; i < RPW * 25; i += 32) {
            int r = i / 25, kk = i % 25;
            const float2 v = *(const float2*)(emb + (size_t)sidx[w][r] * EMBED + kk * 2);
            shx[w][r][kk * 2]     = pack2(v.x);
            shx[w][r][kk * 2 + 1] = pack2(v.y);
        }
        __syncwarp();

        // ---- phase B: layer-1 pre-activations (packed pair-columns) ----
        {
            ull ax[RPW], ah[RPW];
            #pragma unroll
            for (int r = 0; r < RPW; r++) { ax[r] = bz1; ah[r] = br1; }
            #pragma unroll
            for (int k = 0; k < EMBED; k++) {
                ull wv = sW1p[k][j];
                #pragma unroll
                for (int r = 0; r < RPW; r++) ax[r] = ffma2(shx[w][r][k], wv, ax[r]);
            }
            #pragma unroll
            for (int k = 0; k < HID; k++) {
                ull uv = sU1p[k][j];
                #pragma unroll
                for (int r = 0; r < RPW; r++) ah[r] = ffma2(sh1[w][r][k], uv, ah[r]);
            }
            #pragma unroll
            for (int r = 0; r < RPW; r++) {
                float mxl, mxh, mhl, mhh;
                unpk(ax[r], mxl, mxh); unpk(ah[r], mhl, mhh);
                ss[w][r][j] = mxl + mhl;         // col j < 40: z or r -> sum
                int c = j + 32;
                if (c < 40) ss[w][r][c] = mxh + mhh;
                else { ss[w][r][c] = mxh; smh[w][r][c - 40] = mhh; }
            }
        }
        __syncwarp();

        // ---- phase C: layer-1 gate update ----
        if (j < HID) {
            #pragma unroll
            for (int r = 0; r < RPW; r++) {
                float z  = sigm(ss[w][r][j]);
                float rr = sigm(ss[w][r][j + 20]);
                float hh = tanh_(ss[w][r][j + 40] + rr * smh[w][r][j]);
                float hp, dum; unpk(sh1[w][r][j], hp, dum);
                float hn = z * hp + (1.f - z) * hh;
                sh1[w][r][j] = pack2(hn);
            }
        }
        __syncwarp();

        // ---- phase D: layer-2 pre-activations ----
        {
            ull ax[RPW], ah[RPW];
            #pragma unroll
            for (int r = 0; r < RPW; r++) { ax[r] = bz2; ah[r] = br2; }
            #pragma unroll
            for (int k = 0; k < HID; k++) {
                ull wv = sW2p[k][j];
                ull uv = sU2p[k][j];
                #pragma unroll
                for (int r = 0; r < RPW; r++) {
                    ax[r] = ffma2(sh1[w][r][k], wv, ax[r]);
                    ah[r] = ffma2(sh2[w][r][k], uv, ah[r]);
                }
            }
            #pragma unroll
            for (int r = 0; r < RPW; r++) {
                float mxl, mxh, mhl, mhh;
                unpk(ax[r], mxl, mxh); unpk(ah[r], mhl, mhh);
                ss[w][r][j] = mxl + mhl;
                int c = j + 32;
                if (c < 40) ss[w][r][c] = mxh + mhh;
                else { ss[w][r][c] = mxh; smh[w][r][c - 40] = mhh; }
            }
        }
        __syncwarp();

        // ---- phase E: layer-2 gate update ----
        if (j < HID) {
            #pragma unroll
            for (int r = 0; r < RPW; r++) {
                float z  = sigm(ss[w][r][j]);
                float rr = sigm(ss[w][r][j + 20]);
                float hh = tanh_(ss[w][r][j + 40] + rr * smh[w][r][j]);
                float hp, dum; unpk(sh2[w][r][j], hp, dum);
                float hn = z * hp + (1.f - z) * hh;
                sh2[w][r][j] = pack2(hn);
            }
        }
        __syncwarp();
    }

    // ---- dense head: logits = h2 @ Wd + bd ----
    if (j < NLABEL) {
        #pragma unroll
        for (int r = 0; r < RPW; r++) {
            float acc = sbd[j];
            #pragma unroll
            for (int k = 0; k < HID; k++) {
                float hv, dum; unpk(sh2[w][r][k], hv, dum);
                acc += hv * sWd[k][j];
            }
            out[(b0 + r) * NLABEL + j] = acc;
        }
    }
}

extern "C" void kernel_launch(void* const* d_in, const int* in_sizes, int n_in,
                              void* d_out, int out_size) {
    const int*   x   = (const int*)d_in[0];
    const float* emb = (const float*)d_in[1];
    const float* W1  = (const float*)d_in[2];
    const float* U1  = (const float*)d_in[3];
    const float* b1  = (const float*)d_in[4];
    const float* W2  = (const float*)d_in[5];
    const float* U2  = (const float*)d_in[6];
    const float* b2  = (const float*)d_in[7];
    const float* Wd  = (const float*)d_in[8];
    const float* bd  = (const float*)d_in[9];
    // d_in[10] = drop_rate (unused; rate 0)
    (void)in_sizes; (void)n_in; (void)out_size;

    wordrnn_kernel<<<BATCHN / (WARPS * RPW), 128>>>(
        x, emb, W1, U1, b1, W2, U2, b2, Wd, bd, (float*)d_out);
}